// round 8
// baseline (speedup 1.0000x reference)
#include <cuda_runtime.h>
#include <math.h>
#include <float.h>

namespace {
constexpr int B_ = 64;    // batch
constexpr int S_ = 128;   // seq len
constexpr int D_ = 128;   // embed dim
constexpr int V_ = 512;   // vocab
constexpr int C_ = 256;   // controller size
constexpr int N_ = 256;   // memory slots
constexpr int M_ = 64;    // memory width
constexpr int PITCH = 65; // smem pitch for mem (bank-conflict-free)
constexpr int T_ = 1024;  // threads per CTA

// stage: 2 buffers x 4 float4-slots x 1024 threads = 32768 floats (128 KB)
constexpr int STG_FLOATS = 2 * 4 * 1024 * 4;
constexpr int SMEM_FLOATS =
    N_ * PITCH     // mem     16640
    + STG_FLOATS   // stage   32768
    + 512          // xin = [emb128 | rv64 | h256 | rv64]
    + 1024         // garr (gate preacts / rv partials)
    + 256 + 256    // wprev, wga
    + 64 * 3       // keys, er, ad
    + 32 + 8;      // red, sc
constexpr size_t SMEM_BYTES = SMEM_FLOATS * sizeof(float);
}

__device__ __forceinline__ float sigm(float x) { return 1.0f / (1.0f + expf(-x)); }
__device__ __forceinline__ float softplus_(float x) { return log1pf(expf(x)); }
__device__ __forceinline__ float hsum4(float4 a) { return (a.x + a.y) + (a.z + a.w); }

__device__ __forceinline__ void cpa16(float4* dst_smem, const float4* src) {
    unsigned d = (unsigned)__cvta_generic_to_shared(dst_smem);
    asm volatile("cp.async.cg.shared.global [%0], [%1], 16;\n" :: "r"(d), "l"(src));
}
__device__ __forceinline__ void cpa_commit() {
    asm volatile("cp.async.commit_group;\n");
}
template <int NN>
__device__ __forceinline__ void cpa_wait() {
    asm volatile("cp.async.wait_group %0;\n" :: "n"(NN));
}

// Block reductions over 1024 threads. Entry sync protects `red`.
__device__ __forceinline__ float blk_sum(float v, float* red) {
#pragma unroll
    for (int o = 16; o; o >>= 1) v += __shfl_xor_sync(0xffffffffu, v, o);
    __syncthreads();
    if ((threadIdx.x & 31) == 0) red[threadIdx.x >> 5] = v;
    __syncthreads();
    float s = red[0];
#pragma unroll
    for (int i = 1; i < 32; ++i) s += red[i];
    return s;
}
__device__ __forceinline__ float blk_max(float v, float* red) {
#pragma unroll
    for (int o = 16; o; o >>= 1) v = fmaxf(v, __shfl_xor_sync(0xffffffffu, v, o));
    __syncthreads();
    if ((threadIdx.x & 31) == 0) red[threadIdx.x >> 5] = v;
    __syncthreads();
    float s = red[0];
#pragma unroll
    for (int i = 1; i < 32; ++i) s = fmaxf(s, red[i]);
    return s;
}

__global__ void __launch_bounds__(T_, 1) ntm_kernel(
    const int* __restrict__ x, const float* __restrict__ emb,
    const float* __restrict__ W_ih, const float* __restrict__ W_hh,
    const float* __restrict__ b_ih, const float* __restrict__ b_hh,
    const float* __restrict__ key_W, const float* __restrict__ key_b,
    const float* __restrict__ beta_W, const float* __restrict__ beta_b,
    const float* __restrict__ gate_W, const float* __restrict__ gate_b,
    const float* __restrict__ shift_W, const float* __restrict__ shift_b,
    const float* __restrict__ gamma_W, const float* __restrict__ gamma_b,
    const float* __restrict__ erase_W, const float* __restrict__ erase_b,
    const float* __restrict__ add_W, const float* __restrict__ add_b,
    const float* __restrict__ out_W, const float* __restrict__ out_b,
    const float* __restrict__ mem_init, float* __restrict__ out)
{
    extern __shared__ float sm[];
    const int tid = threadIdx.x;
    const int b = blockIdx.x;

    float*  mem   = sm;                         // [N_][PITCH]
    float4* stg   = (float4*)(sm + N_ * PITCH); // [2][4][1024] float4
    float*  xin   = sm + N_ * PITCH + STG_FLOATS; // 512
    float*  garr  = xin + 512;                  // 1024
    float*  wprev = garr + 1024;                // 256
    float*  wga   = wprev + N_;                 // 256
    float*  keys  = wga + N_;                   // 64
    float*  er    = keys + M_;                  // 64
    float*  ad    = er + M_;                    // 64
    float*  red   = ad + M_;                    // 32
    float*  sc    = red + 32;                   // 8

#define STGSLOT(bf, j) (stg + ((((bf) << 2) + (j)) << 10) + tid)

    // ---- init state ----
    for (int i = tid; i < N_ * M_; i += T_)
        mem[(i >> 6) * PITCH + (i & 63)] = mem_init[(size_t)b * N_ * M_ + i];
    if (tid < 256) { xin[192 + tid] = 0.0f; wprev[tid] = 0.0f; }
    if (tid < 64)  xin[448 + tid] = 0.0f;   // rv = 0
    float c_reg = 0.0f;                      // valid for tid < 256

    // ---- hoisted constants ----
    const float  gbias = b_ih[tid] + b_hh[tid];
    const float4* wih4 = (const float4*)(W_ih + (size_t)tid * 192); // 48 f4
    const float4* whh4 = (const float4*)(W_hh + (size_t)tid * 256); // 64 f4

    const int orow = tid >> 1, ohalf = tid & 1;
    const float4* ow4 = (const float4*)(out_W + (size_t)orow * 320) + ohalf * 40; // 40 f4
    const float  ob   = out_b[orow];

    const float4* hw4 = (const float4*)key_W;
    float hbias = 0.0f;
    int hkind = -1, hm = 0;
    if (tid < 416) {
        const int ho = tid >> 1;
        if (ho < 64)       { hw4 = (const float4*)(key_W   + (size_t)ho * C_);          hbias = key_b[ho];          hkind = 0; hm = ho; }
        else if (ho < 128) { hw4 = (const float4*)(erase_W + (size_t)(ho - 64) * C_);   hbias = erase_b[ho - 64];   hkind = 1; hm = ho - 64; }
        else if (ho < 192) { hw4 = (const float4*)(add_W   + (size_t)(ho - 128) * C_);  hbias = add_b[ho - 128];    hkind = 2; hm = ho - 128; }
        else if (ho == 192){ hw4 = (const float4*)beta_W;                               hbias = beta_b[0];          hkind = 3; }
        else if (ho == 193){ hw4 = (const float4*)gate_W;                               hbias = gate_b[0];          hkind = 4; }
        else if (ho == 194){ hw4 = (const float4*)gamma_W;                              hbias = gamma_b[0];         hkind = 5; }
        else if (ho < 198) { hw4 = (const float4*)(shift_W + (size_t)(ho - 195) * C_);  hbias = shift_b[ho - 195];  hkind = 6; hm = ho - 195; }
        hw4 += ohalf * 32;  // 32 f4 half-row
    }
    __syncthreads();

    const float4* xin4 = (const float4*)xin;

    for (int t = 0; t < S_; ++t) {
        // ---- prefetch LSTM chunks 0,1 (weight-only, no xin dependency) ----
#pragma unroll
        for (int c = 0; c < 2; ++c) {
            const float4* src = wih4 + (c << 2);
#pragma unroll
            for (int j = 0; j < 4; ++j) cpa16(STGSLOT(c, j), src + j);
            cpa_commit();
        }

        // ---- phase 0: build input vector [emb | rv] ----
        const int tok = x[b * S_ + t];
        if (tid < D_)            xin[tid] = emb[(size_t)tok * D_ + tid];
        else if (tid < D_ + M_)  xin[tid] = xin[320 + tid];
        __syncthreads();

        // ---- phase 1: LSTM gate preacts via cp.async pipeline (28 chunks) ----
        {
            float4 acc = make_float4(0, 0, 0, 0);
            for (int c = 0; c < 27; ++c) {
                cpa_wait<1>();
                const float4* s = STGSLOT(c & 1, 0);
                const float4* xv = xin4 + (c << 2);
#pragma unroll
                for (int j = 0; j < 4; ++j) {
                    const float4 w = s[j << 10];
                    const float4 v = xv[j];
                    acc.x += w.x * v.x; acc.y += w.y * v.y;
                    acc.z += w.z * v.z; acc.w += w.w * v.w;
                }
                const int c2 = c + 2;
                if (c2 < 28) {
                    const float4* src = (c2 < 12) ? (wih4 + (c2 << 2))
                                                  : (whh4 + ((c2 - 12) << 2));
#pragma unroll
                    for (int j = 0; j < 4; ++j) cpa16(STGSLOT(c & 1, j), src + j);
                    cpa_commit();
                }
            }
            cpa_wait<0>();
            {
                const float4* s = STGSLOT(1, 0);
                const float4* xv = xin4 + (27 << 2);
#pragma unroll
                for (int j = 0; j < 4; ++j) {
                    const float4 w = s[j << 10];
                    const float4 v = xv[j];
                    acc.x += w.x * v.x; acc.y += w.y * v.y;
                    acc.z += w.z * v.z; acc.w += w.w * v.w;
                }
            }
            garr[tid] = gbias + hsum4(acc);
        }

        // ---- prefetch head chunks 0,1 (weights only; overlaps cell update) ----
        if (tid < 416) {
#pragma unroll
            for (int c = 0; c < 2; ++c) {
                const float4* src = hw4 + (c << 2);
#pragma unroll
                for (int j = 0; j < 4; ++j) cpa16(STGSLOT(c, j), src + j);
                cpa_commit();
            }
        }
        __syncthreads();

        // ---- cell update (threads < 256; torch gate order i,f,g,o) ----
        if (tid < 256) {
            const float ig = sigm(garr[tid]);
            const float fg = sigm(garr[256 + tid]);
            const float gg = tanhf(garr[512 + tid]);
            const float og = sigm(garr[768 + tid]);
            c_reg = fg * c_reg + ig * gg;
            xin[192 + tid] = og * tanhf(c_reg);
        }
        __syncthreads();

        // ---- phase 2: head projections via cp.async (8 chunks of 4 f4) ----
        if (tid < 416) {
            float4 acc = make_float4(0, 0, 0, 0);
            const float4* h4 = xin4 + 48 + ohalf * 32;
            for (int c = 0; c < 7; ++c) {
                cpa_wait<1>();
                const float4* s = STGSLOT(c & 1, 0);
                const float4* xv = h4 + (c << 2);
#pragma unroll
                for (int j = 0; j < 4; ++j) {
                    const float4 w = s[j << 10];
                    const float4 v = xv[j];
                    acc.x += w.x * v.x; acc.y += w.y * v.y;
                    acc.z += w.z * v.z; acc.w += w.w * v.w;
                }
                const int c2 = c + 2;
                if (c2 < 8) {
                    const float4* src = hw4 + (c2 << 2);
#pragma unroll
                    for (int j = 0; j < 4; ++j) cpa16(STGSLOT(c & 1, j), src + j);
                    cpa_commit();
                }
            }
            cpa_wait<0>();
            {
                const float4* s = STGSLOT(1, 0);
                const float4* xv = h4 + 28;
#pragma unroll
                for (int j = 0; j < 4; ++j) {
                    const float4 w = s[j << 10];
                    const float4 v = xv[j];
                    acc.x += w.x * v.x; acc.y += w.y * v.y;
                    acc.z += w.z * v.z; acc.w += w.w * v.w;
                }
            }
            float d = hsum4(acc);
            d += __shfl_down_sync(0xffffffffu, d, 1);
            if (hkind >= 0 && ohalf == 0) {
                d += hbias;
                switch (hkind) {
                    case 0: keys[hm] = d; break;
                    case 1: er[hm] = sigm(d); break;
                    case 2: ad[hm] = tanhf(d); break;
                    case 3: sc[0] = softplus_(d); break;
                    case 4: sc[1] = sigm(d); break;
                    case 5: sc[2] = 1.0f + softplus_(d); break;
                    case 6: sc[4 + hm] = d; break;
                }
            }
        }

        // ---- prefetch out-proj chunks 0,1 (overlaps addressing phases) ----
#pragma unroll
        for (int c = 0; c < 2; ++c) {
            const float4* src = ow4 + (c << 2);
#pragma unroll
            for (int j = 0; j < 4; ++j) cpa16(STGSLOT(c, j), src + j);
            cpa_commit();
        }
        __syncthreads();

        // ---- phase 3: shift softmax (t0) + key norm (warp 1) ----
        if (tid == 0) {
            const float s0 = sc[4], s1 = sc[5], s2 = sc[6];
            const float mx = fmaxf(s0, fmaxf(s1, s2));
            const float e0 = expf(s0 - mx), e1 = expf(s1 - mx), e2 = expf(s2 - mx);
            const float inv = 1.0f / (e0 + e1 + e2);
            sc[4] = e0 * inv; sc[5] = e1 * inv; sc[6] = e2 * inv;
        } else if (tid >= 32 && tid < 64) {
            const int l = tid - 32;
            float v = keys[l] * keys[l] + keys[l + 32] * keys[l + 32];
#pragma unroll
            for (int o = 16; o; o >>= 1) v += __shfl_xor_sync(0xffffffffu, v, o);
            if (l == 0) sc[3] = fmaxf(sqrtf(v), 1e-12f);
        }
        __syncthreads();

        const float beta = sc[0], gatev = sc[1], gammav = sc[2], knorm = sc[3];
        const float sh0 = sc[4], sh1 = sc[5], sh2 = sc[6];

        // ---- phase 4: content addressing (4 threads per slot) ----
        {
            const int slot = tid >> 2, q = tid & 3;
            const float* mrow = mem + slot * PITCH + q * 16;
            const float* kq = keys + q * 16;
            float dot = 0.0f, sq = 0.0f;
#pragma unroll
            for (int j = 0; j < 16; ++j) {
                const float v = mrow[j];
                dot += v * kq[j];
                sq += v * v;
            }
            dot += __shfl_xor_sync(0xffffffffu, dot, 1);
            dot += __shfl_xor_sync(0xffffffffu, dot, 2);
            sq  += __shfl_xor_sync(0xffffffffu, sq, 1);
            sq  += __shfl_xor_sync(0xffffffffu, sq, 2);
            const float sim = dot / (fmaxf(sqrtf(sq), 1e-12f) * knorm);
            const float logit = beta * sim;
            const float mx = blk_max(q == 0 ? logit : -FLT_MAX, red);
            const float e = expf(logit - mx);
            const float ssum = blk_sum(q == 0 ? e : 0.0f, red);
            if (q == 0) {
                const float wc = e / ssum;
                wga[slot] = gatev * wc + (1.0f - gatev) * wprev[slot];
            }
        }
        __syncthreads();

        // ---- phase 5: circular conv + sharpening (threads < 256) ----
        {
            float ws = 0.0f;
            if (tid < 256) {
                const float wt = sh0 * wga[(tid + 1) & 255] + sh1 * wga[tid]
                               + sh2 * wga[(tid + 255) & 255];
                ws = powf(wt, gammav);
            }
            const float wsum = blk_sum(ws, red);
            if (tid < 256) {
                const float w = ws / wsum;
                wprev[tid] = w;
                wga[tid] = w;
            }
        }
        __syncthreads();

        // ---- phase 6: rv = w @ mem (16 n-groups x 64 m) ----
        {
            const int m = tid & 63, g = tid >> 6;
            const float* base = mem + (g * 16) * PITCH + m;
            const float* wp = wga + g * 16;
            float s = 0.0f;
#pragma unroll
            for (int n = 0; n < 16; ++n) s += wp[n] * base[n * PITCH];
            garr[g * 64 + m] = s;
        }
        __syncthreads();

        if (tid < 64) {
            float r = 0.0f;
#pragma unroll
            for (int g = 0; g < 16; ++g) r += garr[g * 64 + tid];
            xin[448 + tid] = r;
        }

        // ---- phase 7: memory erase/add (4 threads per slot) ----
        {
            const int slot = tid >> 2, q = tid & 3;
            const float wn = wga[slot];
            float* mrow = mem + slot * PITCH + q * 16;
            const float* eq = er + q * 16;
            const float* aq = ad + q * 16;
#pragma unroll
            for (int j = 0; j < 16; ++j)
                mrow[j] = mrow[j] * (1.0f - wn * eq[j]) + wn * aq[j];
        }
        __syncthreads();

        // ---- phase 8: output logits via cp.async (10 chunks of 4 f4) ----
        {
            float4 acc = make_float4(0, 0, 0, 0);
            const float4* v4 = xin4 + 48 + ohalf * 40;
            for (int c = 0; c < 9; ++c) {
                cpa_wait<1>();
                const float4* s = STGSLOT(c & 1, 0);
                const float4* xv = v4 + (c << 2);
#pragma unroll
                for (int j = 0; j < 4; ++j) {
                    const float4 w = s[j << 10];
                    const float4 v = xv[j];
                    acc.x += w.x * v.x; acc.y += w.y * v.y;
                    acc.z += w.z * v.z; acc.w += w.w * v.w;
                }
                const int c2 = c + 2;
                if (c2 < 10) {
                    const float4* src = ow4 + (c2 << 2);
#pragma unroll
                    for (int j = 0; j < 4; ++j) cpa16(STGSLOT(c & 1, j), src + j);
                    cpa_commit();
                }
            }
            cpa_wait<0>();
            {
                const float4* s = STGSLOT(1, 0);
                const float4* xv = v4 + 36;
#pragma unroll
                for (int j = 0; j < 4; ++j) {
                    const float4 w = s[j << 10];
                    const float4 v = xv[j];
                    acc.x += w.x * v.x; acc.y += w.y * v.y;
                    acc.z += w.z * v.z; acc.w += w.w * v.w;
                }
            }
            float d = hsum4(acc);
            d += __shfl_down_sync(0xffffffffu, d, 1);
            if (ohalf == 0)
                out[((size_t)b * S_ + t) * V_ + orow] = d + ob;
        }
        __syncthreads();
    }
#undef STGSLOT
}

extern "C" void kernel_launch(void* const* d_in, const int* in_sizes, int n_in,
                              void* d_out, int out_size)
{
    const int*   x       = (const int*)d_in[0];
    const float* emb     = (const float*)d_in[1];
    const float* W_ih    = (const float*)d_in[2];
    const float* W_hh    = (const float*)d_in[3];
    const float* b_ih    = (const float*)d_in[4];
    const float* b_hh    = (const float*)d_in[5];
    const float* key_W   = (const float*)d_in[6];
    const float* key_b   = (const float*)d_in[7];
    const float* beta_W  = (const float*)d_in[8];
    const float* beta_b  = (const float*)d_in[9];
    const float* gate_W  = (const float*)d_in[10];
    const float* gate_b  = (const float*)d_in[11];
    const float* shift_W = (const float*)d_in[12];
    const float* shift_b = (const float*)d_in[13];
    const float* gamma_W = (const float*)d_in[14];
    const float* gamma_b = (const float*)d_in[15];
    const float* erase_W = (const float*)d_in[16];
    const float* erase_b = (const float*)d_in[17];
    const float* add_W   = (const float*)d_in[18];
    const float* add_b   = (const float*)d_in[19];
    const float* out_W   = (const float*)d_in[20];
    const float* out_b   = (const float*)d_in[21];
    const float* mem_init= (const float*)d_in[22];
    float* out = (float*)d_out;

    cudaFuncSetAttribute(ntm_kernel, cudaFuncAttributeMaxDynamicSharedMemorySize,
                         (int)SMEM_BYTES);
    ntm_kernel<<<B_, T_, SMEM_BYTES>>>(
        x, emb, W_ih, W_hh, b_ih, b_hh,
        key_W, key_b, beta_W, beta_b, gate_W, gate_b,
        shift_W, shift_b, gamma_W, gamma_b,
        erase_W, erase_b, add_W, add_b,
        out_W, out_b, mem_init, out);
}

// round 11
// speedup vs baseline: 5.5609x; 5.5609x over previous
#include <cuda_runtime.h>
#include <math.h>
#include <float.h>

namespace {
constexpr int B_ = 64;    // batch
constexpr int S_ = 128;   // seq len
constexpr int D_ = 128;   // embed dim
constexpr int V_ = 512;   // vocab
constexpr int N_ = 256;   // memory slots
constexpr int M_ = 64;    // memory width
constexpr int PITCH = 65; // smem pitch for mem (bank-conflict-free)
constexpr int T_ = 512;   // threads per CTA (16 warps)

constexpr int SMEM_FLOATS =
    N_ * PITCH   // mem 16640
    + 512        // xin = [emb128 | rv64 | h256 | rv64]
    + 1024       // garr (gate preacts / rv partials)
    + 1024       // bias (LSTM gate biases)
    + 512        // ob (out biases)
    + 224        // hb (head biases, padded)
    + 256 + 256  // wprev, wga
    + 64 * 3     // keys, er, ad
    + 16 + 8;    // red, sc
constexpr size_t SMEM_BYTES = SMEM_FLOATS * sizeof(float);
}

// fp32 repacked weights (static device scratch; no allocation)
__device__ float g_lstm[1024 * 448];   // row = [W_ih row(192) | W_hh row(256)]
__device__ float g_heads[198 * 256];   // ho-major packed head rows

__global__ void prep_kernel(
    const float* __restrict__ W_ih, const float* __restrict__ W_hh,
    const float* __restrict__ key_W, const float* __restrict__ erase_W,
    const float* __restrict__ add_W, const float* __restrict__ beta_W,
    const float* __restrict__ gate_W, const float* __restrict__ gamma_W,
    const float* __restrict__ shift_W)
{
    const int stride = blockDim.x * gridDim.x;
    const int t0 = blockIdx.x * blockDim.x + threadIdx.x;
    for (int i = t0; i < 1024 * 448; i += stride) {
        const int row = i / 448, k = i - row * 448;
        g_lstm[i] = (k < 192) ? W_ih[row * 192 + k] : W_hh[row * 256 + (k - 192)];
    }
    for (int i = t0; i < 198 * 256; i += stride) {
        const int ho = i >> 8, k = i & 255;
        float v;
        if (ho < 64)        v = key_W[ho * 256 + k];
        else if (ho < 128)  v = erase_W[(ho - 64) * 256 + k];
        else if (ho < 192)  v = add_W[(ho - 128) * 256 + k];
        else if (ho == 192) v = beta_W[k];
        else if (ho == 193) v = gate_W[k];
        else if (ho == 194) v = gamma_W[k];
        else                v = shift_W[(ho - 195) * 256 + k];
        g_heads[i] = v;
    }
}

__device__ __forceinline__ float sigm(float x) { return 1.0f / (1.0f + expf(-x)); }
__device__ __forceinline__ float softplus_(float x) { return log1pf(expf(x)); }

__device__ __forceinline__ float rsum(float v) {
#pragma unroll
    for (int o = 16; o; o >>= 1) v += __shfl_xor_sync(0xffffffffu, v, o);
    return v;
}

// Block reductions over 512 threads (16 warps). Entry sync protects `red`.
__device__ __forceinline__ float blk_sum(float v, float* red) {
    v = rsum(v);
    __syncthreads();
    if ((threadIdx.x & 31) == 0) red[threadIdx.x >> 5] = v;
    __syncthreads();
    float s = red[0];
#pragma unroll
    for (int i = 1; i < 16; ++i) s += red[i];
    return s;
}
__device__ __forceinline__ float blk_max(float v, float* red) {
#pragma unroll
    for (int o = 16; o; o >>= 1) v = fmaxf(v, __shfl_xor_sync(0xffffffffu, v, o));
    __syncthreads();
    if ((threadIdx.x & 31) == 0) red[threadIdx.x >> 5] = v;
    __syncthreads();
    float s = red[0];
#pragma unroll
    for (int i = 1; i < 16; ++i) s = fmaxf(s, red[i]);
    return s;
}

__global__ void __launch_bounds__(T_, 1) ntm_kernel(
    const int* __restrict__ x, const float* __restrict__ emb,
    const float* __restrict__ b_ih, const float* __restrict__ b_hh,
    const float* __restrict__ key_b, const float* __restrict__ beta_b,
    const float* __restrict__ gate_b, const float* __restrict__ shift_b,
    const float* __restrict__ gamma_b, const float* __restrict__ erase_b,
    const float* __restrict__ add_b, const float* __restrict__ out_b,
    const float* __restrict__ out_W,
    const float* __restrict__ mem_init, float* __restrict__ out)
{
    extern __shared__ float sm[];
    const int tid = threadIdx.x;
    const int lane = tid & 31;
    const int wi = tid >> 5;          // warp 0..15
    const int b = blockIdx.x;

    float* mem   = sm;                 // [N_][PITCH]
    float* xin   = mem + N_ * PITCH;   // 512: [emb128 | rv64 | h256 | rv64]
    float* garr  = xin + 512;          // 1024 (preacts / rv partials)
    float* bias  = garr + 1024;        // 1024
    float* ob    = bias + 1024;        // 512
    float* hb    = ob + 512;           // 224
    float* wprev = hb + 224;           // 256
    float* wga   = wprev + N_;         // 256
    float* keys  = wga + N_;           // 64
    float* er    = keys + M_;          // 64
    float* ad    = er + M_;            // 64
    float* red   = ad + M_;            // 16
    float* sc    = red + 16;           // 8: beta,gate,gamma,knorm,sh0..2

    // ---- init state & cached biases ----
    for (int i = tid; i < N_ * M_; i += T_)
        mem[(i >> 6) * PITCH + (i & 63)] = mem_init[(size_t)b * N_ * M_ + i];
    bias[tid]       = b_ih[tid]       + b_hh[tid];
    bias[512 + tid] = b_ih[512 + tid] + b_hh[512 + tid];
    ob[tid] = out_b[tid];
    if (tid < 198) {
        float v;
        if (tid < 64)        v = key_b[tid];
        else if (tid < 128)  v = erase_b[tid - 64];
        else if (tid < 192)  v = add_b[tid - 128];
        else if (tid == 192) v = beta_b[0];
        else if (tid == 193) v = gate_b[0];
        else if (tid == 194) v = gamma_b[0];
        else                 v = shift_b[tid - 195];
        hb[tid] = v;
    }
    if (tid < 256) { xin[192 + tid] = 0.0f; wprev[tid] = 0.0f; }
    if (tid < 64)  xin[448 + tid] = 0.0f;   // rv = 0
    float c_reg = 0.0f;                      // valid for tid < 256
    __syncthreads();

    for (int t = 0; t < S_; ++t) {
        // ---- phase 0: build input vector [emb | rv] ----
        const int tok = x[b * S_ + t];
        if (tid < D_)            xin[tid] = emb[(size_t)tok * D_ + tid];
        else if (tid < D_ + M_)  xin[tid] = xin[320 + tid];
        __syncthreads();

        // ---- phase 1: LSTM preacts, warp-per-row coalesced (64 rows/warp) ----
        {
            const float2* xin2 = (const float2*)xin;
            float2 xr[7];
#pragma unroll
            for (int j = 0; j < 7; ++j) xr[j] = xin2[lane + 32 * j];
            const int base = wi * 64;
            const float2* wbase = (const float2*)g_lstm + (size_t)base * 224 + lane;
            for (int rr = 0; rr < 64; rr += 4) {
                const float2* w0 = wbase + (size_t)rr * 224;
                const float2* w1 = w0 + 224;
                const float2* w2 = w1 + 224;
                const float2* w3 = w2 + 224;
                float p0 = 0.f, p1 = 0.f, p2 = 0.f, p3 = 0.f;
#pragma unroll
                for (int j = 0; j < 7; ++j) {
                    const float2 a0 = w0[32 * j], a1 = w1[32 * j];
                    const float2 a2 = w2[32 * j], a3 = w3[32 * j];
                    const float2 xv = xr[j];
                    p0 = fmaf(a0.x, xv.x, p0); p0 = fmaf(a0.y, xv.y, p0);
                    p1 = fmaf(a1.x, xv.x, p1); p1 = fmaf(a1.y, xv.y, p1);
                    p2 = fmaf(a2.x, xv.x, p2); p2 = fmaf(a2.y, xv.y, p2);
                    p3 = fmaf(a3.x, xv.x, p3); p3 = fmaf(a3.y, xv.y, p3);
                }
                p0 = rsum(p0); p1 = rsum(p1); p2 = rsum(p2); p3 = rsum(p3);
                if (lane == 0) {
                    garr[base + rr]     = p0;
                    garr[base + rr + 1] = p1;
                    garr[base + rr + 2] = p2;
                    garr[base + rr + 3] = p3;
                }
            }
        }
        __syncthreads();

        // ---- cell update (tid < 256; torch gate order i,f,g,o) ----
        if (tid < 256) {
            const float ig = sigm(garr[tid]       + bias[tid]);
            const float fg = sigm(garr[256 + tid] + bias[256 + tid]);
            const float gg = tanhf(garr[512 + tid] + bias[512 + tid]);
            const float og = sigm(garr[768 + tid] + bias[768 + tid]);
            c_reg = fg * c_reg + ig * gg;
            xin[192 + tid] = og * tanhf(c_reg);
        }
        __syncthreads();

        // ---- phase 2: head projections, warp per output ----
        {
            const float4* h4 = (const float4*)(xin + 192);
            const float4 h0 = h4[lane], h1 = h4[lane + 32];
            for (int ho = wi; ho < 198; ho += 16) {
                const float4* wr = (const float4*)g_heads + (size_t)ho * 64 + lane;
                const float4 a = wr[0], c = wr[32];
                float p = fmaf(a.x, h0.x, fmaf(a.y, h0.y, fmaf(a.z, h0.z, a.w * h0.w)));
                p = fmaf(c.x, h1.x, fmaf(c.y, h1.y, fmaf(c.z, h1.z, fmaf(c.w, h1.w, p))));
                p = rsum(p);
                if (lane == 0) {
                    const float d = p + hb[ho];
                    if (ho < 64)        keys[ho] = d;
                    else if (ho < 128)  er[ho - 64] = sigm(d);
                    else if (ho < 192)  ad[ho - 128] = tanhf(d);
                    else if (ho == 192) sc[0] = softplus_(d);
                    else if (ho == 193) sc[1] = sigm(d);
                    else if (ho == 194) sc[2] = 1.0f + softplus_(d);
                    else                sc[4 + ho - 195] = d;
                }
            }
        }
        __syncthreads();

        // ---- phase 3: shift softmax (t0) + key norm (warp 1) ----
        if (tid == 0) {
            const float s0 = sc[4], s1 = sc[5], s2 = sc[6];
            const float mx = fmaxf(s0, fmaxf(s1, s2));
            const float e0 = expf(s0 - mx), e1 = expf(s1 - mx), e2 = expf(s2 - mx);
            const float inv = 1.0f / (e0 + e1 + e2);
            sc[4] = e0 * inv; sc[5] = e1 * inv; sc[6] = e2 * inv;
        } else if (tid >= 32 && tid < 64) {
            const int l = tid - 32;
            float v = keys[l] * keys[l] + keys[l + 32] * keys[l + 32];
#pragma unroll
            for (int o = 16; o; o >>= 1) v += __shfl_xor_sync(0xffffffffu, v, o);
            if (l == 0) sc[3] = fmaxf(sqrtf(v), 1e-12f);
        }
        __syncthreads();

        const float beta = sc[0], gatev = sc[1], gammav = sc[2], knorm = sc[3];
        const float sh0 = sc[4], sh1 = sc[5], sh2 = sc[6];

        // ---- phase 4: content addressing (2 threads per slot) ----
        {
            const int slot = tid >> 1, q = tid & 1;
            const float* mrow = mem + slot * PITCH + q * 32;
            const float* kq = keys + q * 32;
            float dot = 0.0f, sq = 0.0f;
#pragma unroll 8
            for (int j = 0; j < 32; ++j) {
                const float v = mrow[j];
                dot += v * kq[j];
                sq += v * v;
            }
            dot += __shfl_xor_sync(0xffffffffu, dot, 1);
            sq  += __shfl_xor_sync(0xffffffffu, sq, 1);
            const float sim = dot / (fmaxf(sqrtf(sq), 1e-12f) * knorm);
            const float logit = beta * sim;
            const float mx = blk_max(q == 0 ? logit : -FLT_MAX, red);
            const float e = expf(logit - mx);
            const float ssum = blk_sum(q == 0 ? e : 0.0f, red);
            if (q == 0) {
                const float wc = e / ssum;
                wga[slot] = gatev * wc + (1.0f - gatev) * wprev[slot];
            }
        }
        __syncthreads();

        // ---- phase 5: circular conv + sharpening (tid < 256) ----
        {
            float ws = 0.0f;
            if (tid < 256) {
                const float wt = sh0 * wga[(tid + 1) & 255] + sh1 * wga[tid]
                               + sh2 * wga[(tid + 255) & 255];
                ws = powf(wt, gammav);
            }
            const float wsum = blk_sum(ws, red);
            if (tid < 256) {
                const float w = ws / wsum;
                wprev[tid] = w;
                wga[tid] = w;
            }
        }
        __syncthreads();

        // ---- phase 6: rv = w @ mem (8 n-groups x 64 m) ----
        {
            const int m = tid & 63, g = tid >> 6;
            const float* base = mem + (g * 32) * PITCH + m;
            const float* wp = wga + g * 32;
            float s = 0.0f;
#pragma unroll 8
            for (int n = 0; n < 32; ++n) s += wp[n] * base[n * PITCH];
            garr[g * 64 + m] = s;
        }
        __syncthreads();

        if (tid < 64) {
            float r = 0.0f;
#pragma unroll
            for (int g = 0; g < 8; ++g) r += garr[g * 64 + tid];
            xin[448 + tid] = r;
        }

        // ---- phase 7: memory erase/add (2 threads per slot) ----
        {
            const int slot = tid >> 1, q = tid & 1;
            const float wn = wga[slot];
            float* mrow = mem + slot * PITCH + q * 32;
            const float* eq = er + q * 32;
            const float* aq = ad + q * 32;
#pragma unroll 8
            for (int j = 0; j < 32; ++j)
                mrow[j] = mrow[j] * (1.0f - wn * eq[j]) + wn * aq[j];
        }
        __syncthreads();   // rv + mem visible

        // ---- phase 8: output logits, warp per vocab row (32 rows/warp) ----
        {
            const float2* v2 = (const float2*)(xin + 192);   // [h|rv] = 160 f2
            float2 vr[5];
#pragma unroll
            for (int j = 0; j < 5; ++j) vr[j] = v2[lane + 32 * j];
            float* orow = out + ((size_t)b * S_ + t) * V_;
            const int obase = wi * 32;
            const float2* wbase = (const float2*)out_W + (size_t)obase * 160 + lane;
            for (int oo = 0; oo < 32; oo += 2) {
                const float2* w0 = wbase + (size_t)oo * 160;
                const float2* w1 = w0 + 160;
                float p0 = 0.f, p1 = 0.f;
#pragma unroll
                for (int j = 0; j < 5; ++j) {
                    const float2 a0 = w0[32 * j], a1 = w1[32 * j];
                    const float2 xv = vr[j];
                    p0 = fmaf(a0.x, xv.x, p0); p0 = fmaf(a0.y, xv.y, p0);
                    p1 = fmaf(a1.x, xv.x, p1); p1 = fmaf(a1.y, xv.y, p1);
                }
                p0 = rsum(p0); p1 = rsum(p1);
                if (lane == 0) {
                    orow[obase + oo]     = p0 + ob[obase + oo];
                    orow[obase + oo + 1] = p1 + ob[obase + oo + 1];
                }
            }
        }
        __syncthreads();
    }
}

extern "C" void kernel_launch(void* const* d_in, const int* in_sizes, int n_in,
                              void* d_out, int out_size)
{
    const int*   x       = (const int*)d_in[0];
    const float* emb     = (const float*)d_in[1];
    const float* W_ih    = (const float*)d_in[2];
    const float* W_hh    = (const float*)d_in[3];
    const float* b_ih    = (const float*)d_in[4];
    const float* b_hh    = (const float*)d_in[5];
    const float* key_W   = (const float*)d_in[6];
    const float* key_b   = (const float*)d_in[7];
    const float* beta_W  = (const float*)d_in[8];
    const float* beta_b  = (const float*)d_in[9];
    const float* gate_W  = (const float*)d_in[10];
    const float* gate_b  = (const float*)d_in[11];
    const float* shift_W = (const float*)d_in[12];
    const float* shift_b = (const float*)d_in[13];
    const float* gamma_W = (const float*)d_in[14];
    const float* gamma_b = (const float*)d_in[15];
    const float* erase_W = (const float*)d_in[16];
    const float* erase_b = (const float*)d_in[17];
    const float* add_W   = (const float*)d_in[18];
    const float* add_b   = (const float*)d_in[19];
    const float* out_W   = (const float*)d_in[20];
    const float* out_b   = (const float*)d_in[21];
    const float* mem_init= (const float*)d_in[22];
    float* out = (float*)d_out;

    prep_kernel<<<256, 512>>>(W_ih, W_hh, key_W, erase_W, add_W,
                              beta_W, gate_W, gamma_W, shift_W);

    cudaFuncSetAttribute(ntm_kernel, cudaFuncAttributeMaxDynamicSharedMemorySize,
                         (int)SMEM_BYTES);
    ntm_kernel<<<B_, T_, SMEM_BYTES>>>(
        x, emb, b_ih, b_hh,
        key_b, beta_b, gate_b, shift_b, gamma_b, erase_b, add_b, out_b,
        out_W, mem_init, out);
}

// round 12
// speedup vs baseline: 8.0179x; 1.4418x over previous
#include <cuda_runtime.h>
#include <math.h>
#include <float.h>

namespace {
constexpr int B_ = 64;    // batch
constexpr int S_ = 128;   // seq len
constexpr int D_ = 128;   // embed dim
constexpr int V_ = 512;   // vocab
constexpr int N_ = 256;   // memory slots
constexpr int M_ = 64;    // memory width
constexpr int PITCH = 65; // smem pitch for mem (bank-conflict-free)
constexpr int T_ = 512;   // threads per CTA (16 warps)

constexpr int SMEM_FLOATS =
    N_ * PITCH   // mem 16640
    + 512        // xin = [emb128 | rv64 | h256 | rv64]
    + 1024       // garr (gate preacts)
    + 512        // rvp (rv partials; separate from garr: peer DSMEM-writes garr)
    + 1024       // bias (LSTM gate biases)
    + 512        // ob (out biases)
    + 224        // hb (head biases, padded)
    + 256 + 256  // wprev, wga
    + 64 * 3     // keys, er, ad
    + 16 + 8;    // red, sc
constexpr size_t SMEM_BYTES = SMEM_FLOATS * sizeof(float);
}

// fp32 repacked weights (static device scratch; no allocation)
__device__ float g_lstm[1024 * 448];   // row = [W_ih row(192) | W_hh row(256)]
__device__ float g_heads[198 * 256];   // ho-major packed head rows

__global__ void prep_kernel(
    const float* __restrict__ W_ih, const float* __restrict__ W_hh,
    const float* __restrict__ key_W, const float* __restrict__ erase_W,
    const float* __restrict__ add_W, const float* __restrict__ beta_W,
    const float* __restrict__ gate_W, const float* __restrict__ gamma_W,
    const float* __restrict__ shift_W)
{
    const int stride = blockDim.x * gridDim.x;
    const int t0 = blockIdx.x * blockDim.x + threadIdx.x;
    for (int i = t0; i < 1024 * 448; i += stride) {
        const int row = i / 448, k = i - row * 448;
        g_lstm[i] = (k < 192) ? W_ih[row * 192 + k] : W_hh[row * 256 + (k - 192)];
    }
    for (int i = t0; i < 198 * 256; i += stride) {
        const int ho = i >> 8, k = i & 255;
        float v;
        if (ho < 64)        v = key_W[ho * 256 + k];
        else if (ho < 128)  v = erase_W[(ho - 64) * 256 + k];
        else if (ho < 192)  v = add_W[(ho - 128) * 256 + k];
        else if (ho == 192) v = beta_W[k];
        else if (ho == 193) v = gate_W[k];
        else if (ho == 194) v = gamma_W[k];
        else                v = shift_W[(ho - 195) * 256 + k];
        g_heads[i] = v;
    }
}

__device__ __forceinline__ float sigm(float x) { return 1.0f / (1.0f + expf(-x)); }
__device__ __forceinline__ float softplus_(float x) { return log1pf(expf(x)); }

__device__ __forceinline__ float rsum(float v) {
#pragma unroll
    for (int o = 16; o; o >>= 1) v += __shfl_xor_sync(0xffffffffu, v, o);
    return v;
}

__device__ __forceinline__ void cluster_sync_() {
    asm volatile("barrier.cluster.arrive.aligned;" ::: "memory");
    asm volatile("barrier.cluster.wait.aligned;" ::: "memory");
}
// store v into the peer CTA's smem at the same offset as local pointer p
__device__ __forceinline__ void st_peer(float* p, unsigned peer, float v) {
    unsigned a = (unsigned)__cvta_generic_to_shared(p);
    unsigned ra;
    asm volatile("mapa.shared::cluster.u32 %0, %1, %2;" : "=r"(ra) : "r"(a), "r"(peer));
    asm volatile("st.shared::cluster.f32 [%0], %1;" :: "r"(ra), "f"(v) : "memory");
}

// Block reductions over 512 threads (16 warps). Entry sync protects `red`.
__device__ __forceinline__ float blk_sum(float v, float* red) {
    v = rsum(v);
    __syncthreads();
    if ((threadIdx.x & 31) == 0) red[threadIdx.x >> 5] = v;
    __syncthreads();
    float s = red[0];
#pragma unroll
    for (int i = 1; i < 16; ++i) s += red[i];
    return s;
}
__device__ __forceinline__ float blk_max(float v, float* red) {
#pragma unroll
    for (int o = 16; o; o >>= 1) v = fmaxf(v, __shfl_xor_sync(0xffffffffu, v, o));
    __syncthreads();
    if ((threadIdx.x & 31) == 0) red[threadIdx.x >> 5] = v;
    __syncthreads();
    float s = red[0];
#pragma unroll
    for (int i = 1; i < 16; ++i) s = fmaxf(s, red[i]);
    return s;
}

__global__ void __launch_bounds__(T_, 1) __cluster_dims__(2, 1, 1) ntm_kernel(
    const int* __restrict__ x, const float* __restrict__ emb,
    const float* __restrict__ b_ih, const float* __restrict__ b_hh,
    const float* __restrict__ key_b, const float* __restrict__ beta_b,
    const float* __restrict__ gate_b, const float* __restrict__ shift_b,
    const float* __restrict__ gamma_b, const float* __restrict__ erase_b,
    const float* __restrict__ add_b, const float* __restrict__ out_b,
    const float* __restrict__ out_W,
    const float* __restrict__ mem_init, float* __restrict__ out)
{
    extern __shared__ float sm[];
    const int tid = threadIdx.x;
    const int lane = tid & 31;
    const int wi = tid >> 5;          // warp 0..15
    const int b = blockIdx.x >> 1;    // cluster index = batch element
    unsigned rank;
    asm("mov.u32 %0, %%cluster_ctarank;" : "=r"(rank));
    const unsigned peer = rank ^ 1u;

    float* mem   = sm;                 // [N_][PITCH]
    float* xin   = mem + N_ * PITCH;   // 512: [emb128 | rv64 | h256 | rv64]
    float* garr  = xin + 512;          // 1024 gate preacts (peer writes half)
    float* rvp   = garr + 1024;        // 512 rv partials (local only)
    float* bias  = rvp + 512;          // 1024
    float* ob    = bias + 1024;        // 512
    float* hb    = ob + 512;           // 224
    float* wprev = hb + 224;           // 256
    float* wga   = wprev + N_;         // 256
    float* keys  = wga + N_;           // 64
    float* er    = keys + M_;          // 64
    float* ad    = er + M_;            // 64
    float* red   = ad + M_;            // 16
    float* sc    = red + 16;           // 8: beta,gate,gamma,knorm,sh0..2

    // ---- init state & cached biases (duplicated per CTA) ----
    for (int i = tid; i < N_ * M_; i += T_)
        mem[(i >> 6) * PITCH + (i & 63)] = mem_init[(size_t)b * N_ * M_ + i];
    bias[tid]       = b_ih[tid]       + b_hh[tid];
    bias[512 + tid] = b_ih[512 + tid] + b_hh[512 + tid];
    ob[tid] = out_b[tid];
    if (tid < 198) {
        float v;
        if (tid < 64)        v = key_b[tid];
        else if (tid < 128)  v = erase_b[tid - 64];
        else if (tid < 192)  v = add_b[tid - 128];
        else if (tid == 192) v = beta_b[0];
        else if (tid == 193) v = gate_b[0];
        else if (tid == 194) v = gamma_b[0];
        else                 v = shift_b[tid - 195];
        hb[tid] = v;
    }
    if (tid < 256) { xin[192 + tid] = 0.0f; wprev[tid] = 0.0f; }
    if (tid < 64)  xin[448 + tid] = 0.0f;   // rv = 0
    float c_reg = 0.0f;                      // valid for tid < 256
    __syncthreads();

    for (int t = 0; t < S_; ++t) {
        // ---- phase 0: build input vector [emb | rv] ----
        const int tok = x[b * S_ + t];
        if (tid < D_)            xin[tid] = emb[(size_t)tok * D_ + tid];
        else if (tid < D_ + M_)  xin[tid] = xin[320 + tid];
        __syncthreads();

        // ---- phase 1: LSTM preacts; this CTA does rows [rank*512, +512) ----
        {
            const float2* xin2 = (const float2*)xin;
            float2 xr[7];
#pragma unroll
            for (int j = 0; j < 7; ++j) xr[j] = xin2[lane + 32 * j];
            const int base = (int)rank * 512 + wi * 32;
            const float2* wbase = (const float2*)g_lstm + (size_t)base * 224 + lane;
            for (int rr = 0; rr < 32; rr += 4) {
                const float2* w0 = wbase + (size_t)rr * 224;
                const float2* w1 = w0 + 224;
                const float2* w2 = w1 + 224;
                const float2* w3 = w2 + 224;
                float p0 = 0.f, p1 = 0.f, p2 = 0.f, p3 = 0.f;
#pragma unroll
                for (int j = 0; j < 7; ++j) {
                    const float2 a0 = w0[32 * j], a1 = w1[32 * j];
                    const float2 a2 = w2[32 * j], a3 = w3[32 * j];
                    const float2 xv = xr[j];
                    p0 = fmaf(a0.x, xv.x, p0); p0 = fmaf(a0.y, xv.y, p0);
                    p1 = fmaf(a1.x, xv.x, p1); p1 = fmaf(a1.y, xv.y, p1);
                    p2 = fmaf(a2.x, xv.x, p2); p2 = fmaf(a2.y, xv.y, p2);
                    p3 = fmaf(a3.x, xv.x, p3); p3 = fmaf(a3.y, xv.y, p3);
                }
                p0 = rsum(p0); p1 = rsum(p1); p2 = rsum(p2); p3 = rsum(p3);
                if (lane == 0) {
                    garr[base + rr]     = p0;  st_peer(&garr[base + rr],     peer, p0);
                    garr[base + rr + 1] = p1;  st_peer(&garr[base + rr + 1], peer, p1);
                    garr[base + rr + 2] = p2;  st_peer(&garr[base + rr + 2], peer, p2);
                    garr[base + rr + 3] = p3;  st_peer(&garr[base + rr + 3], peer, p3);
                }
            }
        }
        cluster_sync_();   // sync A: full preacts visible in both CTAs

        // ---- cell update (tid < 256; torch gate order i,f,g,o) ----
        if (tid < 256) {
            const float ig = sigm(garr[tid]       + bias[tid]);
            const float fg = sigm(garr[256 + tid] + bias[256 + tid]);
            const float gg = tanhf(garr[512 + tid] + bias[512 + tid]);
            const float og = sigm(garr[768 + tid] + bias[768 + tid]);
            c_reg = fg * c_reg + ig * gg;
            xin[192 + tid] = og * tanhf(c_reg);
        }
        __syncthreads();

        // ---- phase 2: head projections; split 198 outputs across cluster ----
        {
            const float4* h4 = (const float4*)(xin + 192);
            const float4 h0 = h4[lane], h1 = h4[lane + 32];
            for (int ho = (int)rank * 16 + wi; ho < 198; ho += 32) {
                const float4* wr = (const float4*)g_heads + (size_t)ho * 64 + lane;
                const float4 a = wr[0], c = wr[32];
                float p = fmaf(a.x, h0.x, fmaf(a.y, h0.y, fmaf(a.z, h0.z, a.w * h0.w)));
                p = fmaf(c.x, h1.x, fmaf(c.y, h1.y, fmaf(c.z, h1.z, fmaf(c.w, h1.w, p))));
                p = rsum(p);
                if (lane == 0) {
                    const float d = p + hb[ho];
                    float* dst; float val;
                    if (ho < 64)        { dst = &keys[ho];          val = d; }
                    else if (ho < 128)  { dst = &er[ho - 64];       val = sigm(d); }
                    else if (ho < 192)  { dst = &ad[ho - 128];      val = tanhf(d); }
                    else if (ho == 192) { dst = &sc[0];             val = softplus_(d); }
                    else if (ho == 193) { dst = &sc[1];             val = sigm(d); }
                    else if (ho == 194) { dst = &sc[2];             val = 1.0f + softplus_(d); }
                    else                { dst = &sc[4 + ho - 195];  val = d; }
                    *dst = val;
                    st_peer(dst, peer, val);
                }
            }
        }
        cluster_sync_();   // sync B: keys/er/ad/sc complete in both CTAs

        // ---- phase 3: shift softmax (t0) + key norm (warp 1) ----
        if (tid == 0) {
            const float s0 = sc[4], s1 = sc[5], s2 = sc[6];
            const float mx = fmaxf(s0, fmaxf(s1, s2));
            const float e0 = expf(s0 - mx), e1 = expf(s1 - mx), e2 = expf(s2 - mx);
            const float inv = 1.0f / (e0 + e1 + e2);
            sc[4] = e0 * inv; sc[5] = e1 * inv; sc[6] = e2 * inv;
        } else if (tid >= 32 && tid < 64) {
            const int l = tid - 32;
            float v = keys[l] * keys[l] + keys[l + 32] * keys[l + 32];
#pragma unroll
            for (int o = 16; o; o >>= 1) v += __shfl_xor_sync(0xffffffffu, v, o);
            if (l == 0) sc[3] = fmaxf(sqrtf(v), 1e-12f);
        }
        __syncthreads();

        const float beta = sc[0], gatev = sc[1], gammav = sc[2], knorm = sc[3];
        const float sh0 = sc[4], sh1 = sc[5], sh2 = sc[6];

        // ---- phase 4: content addressing (2 threads per slot; replicated) ----
        {
            const int slot = tid >> 1, q = tid & 1;
            const float* mrow = mem + slot * PITCH + q * 32;
            const float* kq = keys + q * 32;
            float dot = 0.0f, sq = 0.0f;
#pragma unroll 8
            for (int j = 0; j < 32; ++j) {
                const float v = mrow[j];
                dot += v * kq[j];
                sq += v * v;
            }
            dot += __shfl_xor_sync(0xffffffffu, dot, 1);
            sq  += __shfl_xor_sync(0xffffffffu, sq, 1);
            const float sim = dot / (fmaxf(sqrtf(sq), 1e-12f) * knorm);
            const float logit = beta * sim;
            const float mx = blk_max(q == 0 ? logit : -FLT_MAX, red);
            const float e = expf(logit - mx);
            const float ssum = blk_sum(q == 0 ? e : 0.0f, red);
            if (q == 0) {
                const float wc = e / ssum;
                wga[slot] = gatev * wc + (1.0f - gatev) * wprev[slot];
            }
        }
        __syncthreads();

        // ---- phase 5: circular conv + sharpening (tid < 256; replicated) ----
        {
            float ws = 0.0f;
            if (tid < 256) {
                const float wt = sh0 * wga[(tid + 1) & 255] + sh1 * wga[tid]
                               + sh2 * wga[(tid + 255) & 255];
                ws = powf(wt, gammav);
            }
            const float wsum = blk_sum(ws, red);
            if (tid < 256) {
                const float w = ws / wsum;
                wprev[tid] = w;
                wga[tid] = w;
            }
        }
        __syncthreads();

        // ---- phase 6: rv = w @ mem (8 n-groups x 64 m; replicated) ----
        {
            const int m = tid & 63, g = tid >> 6;
            const float* base = mem + (g * 32) * PITCH + m;
            const float* wp = wga + g * 32;
            float s = 0.0f;
#pragma unroll 8
            for (int n = 0; n < 32; ++n) s += wp[n] * base[n * PITCH];
            rvp[g * 64 + m] = s;
        }
        __syncthreads();

        if (tid < 64) {
            float r = 0.0f;
#pragma unroll
            for (int g = 0; g < 8; ++g) r += rvp[g * 64 + tid];
            xin[448 + tid] = r;
        }

        // ---- phase 7: memory erase/add (2 threads per slot; replicated) ----
        {
            const int slot = tid >> 1, q = tid & 1;
            const float wn = wga[slot];
            float* mrow = mem + slot * PITCH + q * 32;
            const float* eq = er + q * 32;
            const float* aq = ad + q * 32;
#pragma unroll 8
            for (int j = 0; j < 32; ++j)
                mrow[j] = mrow[j] * (1.0f - wn * eq[j]) + wn * aq[j];
        }
        __syncthreads();   // rv + mem visible

        // ---- phase 8: output logits; this CTA does rows [rank*256, +256) ----
        {
            const float2* v2 = (const float2*)(xin + 192);   // [h|rv] = 160 f2
            float2 vr[5];
#pragma unroll
            for (int j = 0; j < 5; ++j) vr[j] = v2[lane + 32 * j];
            float* orow = out + ((size_t)b * S_ + t) * V_;
            const int obase = (int)rank * 256 + wi * 16;
            const float2* wbase = (const float2*)out_W + (size_t)obase * 160 + lane;
            for (int oo = 0; oo < 16; oo += 2) {
                const float2* w0 = wbase + (size_t)oo * 160;
                const float2* w1 = w0 + 160;
                float p0 = 0.f, p1 = 0.f;
#pragma unroll
                for (int j = 0; j < 5; ++j) {
                    const float2 a0 = w0[32 * j], a1 = w1[32 * j];
                    const float2 xv = vr[j];
                    p0 = fmaf(a0.x, xv.x, p0); p0 = fmaf(a0.y, xv.y, p0);
                    p1 = fmaf(a1.x, xv.x, p1); p1 = fmaf(a1.y, xv.y, p1);
                }
                p0 = rsum(p0); p1 = rsum(p1);
                if (lane == 0) {
                    orow[obase + oo]     = p0 + ob[obase + oo];
                    orow[obase + oo + 1] = p1 + ob[obase + oo + 1];
                }
            }
        }
        __syncthreads();
    }
}

extern "C" void kernel_launch(void* const* d_in, const int* in_sizes, int n_in,
                              void* d_out, int out_size)
{
    const int*   x       = (const int*)d_in[0];
    const float* emb     = (const float*)d_in[1];
    const float* W_ih    = (const float*)d_in[2];
    const float* W_hh    = (const float*)d_in[3];
    const float* b_ih    = (const float*)d_in[4];
    const float* b_hh    = (const float*)d_in[5];
    const float* key_W   = (const float*)d_in[6];
    const float* key_b   = (const float*)d_in[7];
    const float* beta_W  = (const float*)d_in[8];
    const float* beta_b  = (const float*)d_in[9];
    const float* gate_W  = (const float*)d_in[10];
    const float* gate_b  = (const float*)d_in[11];
    const float* shift_W = (const float*)d_in[12];
    const float* shift_b = (const float*)d_in[13];
    const float* gamma_W = (const float*)d_in[14];
    const float* gamma_b = (const float*)d_in[15];
    const float* erase_W = (const float*)d_in[16];
    const float* erase_b = (const float*)d_in[17];
    const float* add_W   = (const float*)d_in[18];
    const float* add_b   = (const float*)d_in[19];
    const float* out_W   = (const float*)d_in[20];
    const float* out_b   = (const float*)d_in[21];
    const float* mem_init= (const float*)d_in[22];
    float* out = (float*)d_out;

    prep_kernel<<<256, 512>>>(W_ih, W_hh, key_W, erase_W, add_W,
                              beta_W, gate_W, gamma_W, shift_W);

    cudaFuncSetAttribute(ntm_kernel, cudaFuncAttributeMaxDynamicSharedMemorySize,
                         (int)SMEM_BYTES);
    ntm_kernel<<<2 * B_, T_, SMEM_BYTES>>>(
        x, emb, b_ih, b_hh,
        key_b, beta_b, gate_b, shift_b, gamma_b, erase_b, add_b, out_b,
        out_W, mem_init, out);
}

// round 13
// speedup vs baseline: 11.0242x; 1.3749x over previous
#include <cuda_runtime.h>
#include <math.h>
#include <float.h>

namespace {
constexpr int B_ = 64;    // batch
constexpr int S_ = 128;   // seq len
constexpr int D_ = 128;   // embed dim
constexpr int V_ = 512;   // vocab
constexpr int N_ = 256;   // memory slots
constexpr int M_ = 64;    // memory width
constexpr int PITCH = 65; // smem pitch for mem (bank-conflict-free)
constexpr int T_ = 512;   // threads per CTA (16 warps)

constexpr int SMEM_FLOATS =
    N_ * PITCH   // mem 16640
    + 512        // xin = [emb128 | rv64 | h256 | rv64]
    + 1024       // garr (gate preacts; peer DSMEM-writes half)
    + 2048       // part (k-chunk partials)
    + 512        // part2 (head partial exchange; peer writes half)
    + 512        // rvp (rv partials)
    + 1024       // bias (LSTM gate biases)
    + 512        // obv (out biases)
    + 256        // hb (head biases)
    + 256 + 256  // wprev, wga
    + 64 * 3     // keys, er, ad
    + 16 + 8;    // red, sc
constexpr size_t SMEM_BYTES = SMEM_FLOATS * sizeof(float);
}

// fp32 transposed weights (static device scratch; no allocation)
__device__ float g_lstmT[448 * 1024];  // [k][gate-row]; k = [emb|rv|h]
__device__ float g_headsT[256 * 256];  // [k][ho], ho >= 198 zero-padded
__device__ float g_outT[320 * 512];    // [k][vocab-row]

__global__ void prep_kernel(
    const float* __restrict__ W_ih, const float* __restrict__ W_hh,
    const float* __restrict__ key_W, const float* __restrict__ erase_W,
    const float* __restrict__ add_W, const float* __restrict__ beta_W,
    const float* __restrict__ gate_W, const float* __restrict__ gamma_W,
    const float* __restrict__ shift_W, const float* __restrict__ out_W)
{
    const int stride = blockDim.x * gridDim.x;
    const int t0 = blockIdx.x * blockDim.x + threadIdx.x;
    for (int i = t0; i < 448 * 1024; i += stride) {
        const int k = i >> 10, row = i & 1023;
        g_lstmT[i] = (k < 192) ? W_ih[row * 192 + k] : W_hh[row * 256 + (k - 192)];
    }
    for (int i = t0; i < 256 * 256; i += stride) {
        const int k = i >> 8, ho = i & 255;
        float v = 0.0f;
        if (ho < 64)        v = key_W[ho * 256 + k];
        else if (ho < 128)  v = erase_W[(ho - 64) * 256 + k];
        else if (ho < 192)  v = add_W[(ho - 128) * 256 + k];
        else if (ho == 192) v = beta_W[k];
        else if (ho == 193) v = gate_W[k];
        else if (ho == 194) v = gamma_W[k];
        else if (ho < 198)  v = shift_W[(ho - 195) * 256 + k];
        g_headsT[i] = v;
    }
    for (int i = t0; i < 320 * 512; i += stride) {
        const int k = i >> 9, row = i & 511;
        g_outT[i] = out_W[row * 320 + k];
    }
}

__device__ __forceinline__ float sigm(float x) { return 1.0f / (1.0f + expf(-x)); }
__device__ __forceinline__ float softplus_(float x) { return log1pf(expf(x)); }

__device__ __forceinline__ void fma4(float4& a, float s, const float4 w) {
    a.x = fmaf(s, w.x, a.x); a.y = fmaf(s, w.y, a.y);
    a.z = fmaf(s, w.z, a.z); a.w = fmaf(s, w.w, a.w);
}

__device__ __forceinline__ float rsum(float v) {
#pragma unroll
    for (int o = 16; o; o >>= 1) v += __shfl_xor_sync(0xffffffffu, v, o);
    return v;
}

__device__ __forceinline__ void cluster_sync_() {
    asm volatile("barrier.cluster.arrive.aligned;" ::: "memory");
    asm volatile("barrier.cluster.wait.aligned;" ::: "memory");
}
// store v into the peer CTA's smem at the same offset as local pointer p
__device__ __forceinline__ void st_peer(float* p, unsigned peer, float v) {
    unsigned a = (unsigned)__cvta_generic_to_shared(p);
    unsigned ra;
    asm volatile("mapa.shared::cluster.u32 %0, %1, %2;" : "=r"(ra) : "r"(a), "r"(peer));
    asm volatile("st.shared::cluster.f32 [%0], %1;" :: "r"(ra), "f"(v) : "memory");
}

// Block sum over 512 threads (16 warps). Entry sync protects `red`.
__device__ __forceinline__ float blk_sum(float v, float* red) {
    v = rsum(v);
    __syncthreads();
    if ((threadIdx.x & 31) == 0) red[threadIdx.x >> 5] = v;
    __syncthreads();
    float s = red[0];
#pragma unroll
    for (int i = 1; i < 16; ++i) s += red[i];
    return s;
}

__global__ void __launch_bounds__(T_, 1) __cluster_dims__(2, 1, 1) ntm_kernel(
    const int* __restrict__ x, const float* __restrict__ emb,
    const float* __restrict__ b_ih, const float* __restrict__ b_hh,
    const float* __restrict__ key_b, const float* __restrict__ beta_b,
    const float* __restrict__ gate_b, const float* __restrict__ shift_b,
    const float* __restrict__ gamma_b, const float* __restrict__ erase_b,
    const float* __restrict__ add_b, const float* __restrict__ out_b,
    const float* __restrict__ mem_init, float* __restrict__ out)
{
    extern __shared__ float sm[];
    const int tid = threadIdx.x;
    const int lane = tid & 31;
    const int wi = tid >> 5;          // warp 0..15
    const int b = blockIdx.x >> 1;    // cluster index = batch element
    unsigned rank;
    asm("mov.u32 %0, %%cluster_ctarank;" : "=r"(rank));
    const unsigned peer = rank ^ 1u;
    const int rk = (int)rank;

    float* mem   = sm;                 // [N_][PITCH]
    float* xin   = mem + N_ * PITCH;   // 512: [emb128 | rv64 | h256 | rv64]
    float* garr  = xin + 512;          // 1024 gate preacts
    float* part  = garr + 1024;        // 2048 partials
    float* part2 = part + 2048;        // 512 head partial exchange
    float* rvp   = part2 + 512;        // 512 rv partials
    float* bias  = rvp + 512;          // 1024
    float* obv   = bias + 1024;        // 512
    float* hb    = obv + 512;          // 256
    float* wprev = hb + 256;           // 256
    float* wga   = wprev + N_;         // 256
    float* keys  = wga + N_;           // 64
    float* er    = keys + M_;          // 64
    float* ad    = er + M_;            // 64
    float* red   = ad + M_;            // 16
    float* sc    = red + 16;           // 8: beta,gate,gamma,knorm,sh0..2

    // ---- init state & cached biases (duplicated per CTA) ----
    for (int i = tid; i < N_ * M_; i += T_)
        mem[(i >> 6) * PITCH + (i & 63)] = mem_init[(size_t)b * N_ * M_ + i];
    bias[tid]       = b_ih[tid]       + b_hh[tid];
    bias[512 + tid] = b_ih[512 + tid] + b_hh[512 + tid];
    obv[tid] = out_b[tid];
    if (tid < 256) {
        float v = 0.0f;
        if (tid < 64)        v = key_b[tid];
        else if (tid < 128)  v = erase_b[tid - 64];
        else if (tid < 192)  v = add_b[tid - 128];
        else if (tid == 192) v = beta_b[0];
        else if (tid == 193) v = gate_b[0];
        else if (tid == 194) v = gamma_b[0];
        else if (tid < 198)  v = shift_b[tid - 195];
        hb[tid] = v;
    }
    if (tid < 256) { xin[192 + tid] = 0.0f; wprev[tid] = 0.0f; }
    if (tid < 64)  xin[448 + tid] = 0.0f;   // rv = 0
    float c_reg = 0.0f;                      // valid for tid < 256
    __syncthreads();

    for (int t = 0; t < S_; ++t) {
        // ---- phase 0: build input vector [emb | rv] ----
        const int tok = x[b * S_ + t];
        if (tid < D_)            xin[tid] = emb[(size_t)tok * D_ + tid];
        else if (tid < D_ + M_)  xin[tid] = xin[320 + tid];
        __syncthreads();

        // ---- phase 1: LSTM preacts, transposed GEMV ----
        // warp = (output-block obk of 128) x (k-chunk kc of 112); my rows = rank half
        {
            const int obk = wi & 3, kc = wi >> 2;
            const int j = rk * 512 + obk * 128 + (lane << 2);
            const float* wt = g_lstmT + (size_t)(kc * 112) * 1024 + j;
            const float4* xv4p = (const float4*)(xin + kc * 112);
            float4 acc = make_float4(0, 0, 0, 0);
#pragma unroll 7
            for (int k = 0; k < 112; k += 4) {
                const float4 w0 = *(const float4*)(wt + (size_t)(k + 0) * 1024);
                const float4 w1 = *(const float4*)(wt + (size_t)(k + 1) * 1024);
                const float4 w2 = *(const float4*)(wt + (size_t)(k + 2) * 1024);
                const float4 w3 = *(const float4*)(wt + (size_t)(k + 3) * 1024);
                const float4 xv = xv4p[k >> 2];
                fma4(acc, xv.x, w0); fma4(acc, xv.y, w1);
                fma4(acc, xv.z, w2); fma4(acc, xv.w, w3);
            }
            ((float4*)(part + kc * 512))[obk * 32 + lane] = acc;
        }
        __syncthreads();
        {
            const float g = (part[tid] + part[512 + tid])
                          + (part[1024 + tid] + part[1536 + tid]);
            garr[rk * 512 + tid] = g;
            st_peer(&garr[rk * 512 + tid], peer, g);
        }
        cluster_sync_();   // sync A: full preacts in both CTAs

        // ---- cell update (tid < 256; torch gate order i,f,g,o) ----
        if (tid < 256) {
            const float ig = sigm(garr[tid]        + bias[tid]);
            const float fg = sigm(garr[256 + tid]  + bias[256 + tid]);
            const float gg = tanhf(garr[512 + tid] + bias[512 + tid]);
            const float og = sigm(garr[768 + tid]  + bias[768 + tid]);
            c_reg = fg * c_reg + ig * gg;
            xin[192 + tid] = og * tanhf(c_reg);
        }
        __syncthreads();

        // ---- phase 2: heads, transposed; k split across cluster ----
        {
            const int hob = wi & 1, kc2 = wi >> 1;           // 2 blocks x 8 chunks
            const int kg0 = rk * 128 + kc2 * 16;
            const float* wt = g_headsT + (size_t)kg0 * 256 + hob * 128 + (lane << 2);
            const float4* xv4p = (const float4*)(xin + 192 + kg0);
            float4 acc = make_float4(0, 0, 0, 0);
#pragma unroll
            for (int k = 0; k < 16; k += 4) {
                const float4 w0 = *(const float4*)(wt + (size_t)(k + 0) * 256);
                const float4 w1 = *(const float4*)(wt + (size_t)(k + 1) * 256);
                const float4 w2 = *(const float4*)(wt + (size_t)(k + 2) * 256);
                const float4 w3 = *(const float4*)(wt + (size_t)(k + 3) * 256);
                const float4 xv = xv4p[k >> 2];
                fma4(acc, xv.x, w0); fma4(acc, xv.y, w1);
                fma4(acc, xv.z, w2); fma4(acc, xv.w, w3);
            }
            ((float4*)(part + kc2 * 256))[hob * 32 + lane] = acc;
        }
        __syncthreads();
        if (tid < 256) {
            float pd = 0.0f;
#pragma unroll
            for (int i = 0; i < 8; ++i) pd += part[i * 256 + tid];
            part2[rk * 256 + tid] = pd;
            st_peer(&part2[rk * 256 + tid], peer, pd);
        }
        cluster_sync_();   // sync B: both k-halves of head dots present
        if (tid < 256) {
            const float d = part2[tid] + part2[256 + tid] + hb[tid];
            if (tid < 64)        keys[tid] = d;
            else if (tid < 128)  er[tid - 64] = sigm(d);
            else if (tid < 192)  ad[tid - 128] = tanhf(d);
            else if (tid == 192) sc[0] = softplus_(d);
            else if (tid == 193) sc[1] = sigm(d);
            else if (tid == 194) sc[2] = 1.0f + softplus_(d);
            else if (tid < 198)  sc[4 + tid - 195] = d;
        }
        __syncthreads();

        // ---- phase 3: shift softmax (t0) + key norm (warp 1) ----
        if (tid == 0) {
            const float s0 = sc[4], s1 = sc[5], s2 = sc[6];
            const float mx = fmaxf(s0, fmaxf(s1, s2));
            const float e0 = expf(s0 - mx), e1 = expf(s1 - mx), e2 = expf(s2 - mx);
            const float inv = 1.0f / (e0 + e1 + e2);
            sc[4] = e0 * inv; sc[5] = e1 * inv; sc[6] = e2 * inv;
        } else if (tid >= 32 && tid < 64) {
            const int l = tid - 32;
            float v = keys[l] * keys[l] + keys[l + 32] * keys[l + 32];
#pragma unroll
            for (int o = 16; o; o >>= 1) v += __shfl_xor_sync(0xffffffffu, v, o);
            if (l == 0) sc[3] = fmaxf(sqrtf(v), 1e-12f);
        }
        __syncthreads();

        const float beta = sc[0], gatev = sc[1], gammav = sc[2], knorm = sc[3];
        const float sh0 = sc[4], sh1 = sc[5], sh2 = sc[6];

        // ---- phase 4: content addressing (2 threads per slot; replicated) ----
        // logits = beta*sim, |sim|<=1, beta bounded small: exp without max-sub
        {
            const int slot = tid >> 1, q = tid & 1;
            const float* mrow = mem + slot * PITCH + q * 32;
            const float* kq = keys + q * 32;
            float dot = 0.0f, sq = 0.0f;
#pragma unroll 8
            for (int j = 0; j < 32; ++j) {
                const float v = mrow[j];
                dot += v * kq[j];
                sq += v * v;
            }
            dot += __shfl_xor_sync(0xffffffffu, dot, 1);
            sq  += __shfl_xor_sync(0xffffffffu, sq, 1);
            const float sim = dot / (fmaxf(sqrtf(sq), 1e-12f) * knorm);
            const float e = expf(beta * sim);
            const float ssum = blk_sum(q == 0 ? e : 0.0f, red);
            if (q == 0) {
                const float wc = e / ssum;
                wga[slot] = gatev * wc + (1.0f - gatev) * wprev[slot];
            }
        }
        __syncthreads();

        // ---- phase 5: circular conv + sharpening (tid < 256; replicated) ----
        {
            float ws = 0.0f;
            if (tid < 256) {
                const float wt_ = sh0 * wga[(tid + 1) & 255] + sh1 * wga[tid]
                                + sh2 * wga[(tid + 255) & 255];
                ws = powf(wt_, gammav);
            }
            const float wsum = blk_sum(ws, red);
            if (tid < 256) {
                const float w = ws / wsum;
                wprev[tid] = w;
                wga[tid] = w;
            }
        }
        __syncthreads();

        // ---- phase 6: rv = w @ mem (8 n-groups x 64 m; replicated) ----
        {
            const int m = tid & 63, g = tid >> 6;
            const float* base = mem + (g * 32) * PITCH + m;
            const float* wp = wga + g * 32;
            float s = 0.0f;
#pragma unroll 8
            for (int n = 0; n < 32; ++n) s += wp[n] * base[n * PITCH];
            rvp[g * 64 + m] = s;
        }
        __syncthreads();

        if (tid < 64) {
            float r = 0.0f;
#pragma unroll
            for (int g = 0; g < 8; ++g) r += rvp[g * 64 + tid];
            xin[448 + tid] = r;
        }

        // ---- phase 7: memory erase/add (2 threads per slot; replicated) ----
        {
            const int slot = tid >> 1, q = tid & 1;
            const float wn = wga[slot];
            float* mrow = mem + slot * PITCH + q * 32;
            const float* eq = er + q * 32;
            const float* aq = ad + q * 32;
#pragma unroll 8
            for (int j = 0; j < 32; ++j)
                mrow[j] = mrow[j] * (1.0f - wn * eq[j]) + wn * aq[j];
        }
        __syncthreads();   // rv + mem visible

        // ---- phase 8: output logits, transposed; rows [rank*256, +256) ----
        {
            const int job = wi & 1, kc3 = wi >> 1;           // 2 blocks x 8 chunks
            const int j0 = rk * 256 + job * 128 + (lane << 2);
            const int kg0 = kc3 * 40;
            const float* wt = g_outT + (size_t)kg0 * 512 + j0;
            const float4* xv4p = (const float4*)(xin + 192 + kg0);
            float4 acc = make_float4(0, 0, 0, 0);
#pragma unroll 5
            for (int k = 0; k < 40; k += 4) {
                const float4 w0 = *(const float4*)(wt + (size_t)(k + 0) * 512);
                const float4 w1 = *(const float4*)(wt + (size_t)(k + 1) * 512);
                const float4 w2 = *(const float4*)(wt + (size_t)(k + 2) * 512);
                const float4 w3 = *(const float4*)(wt + (size_t)(k + 3) * 512);
                const float4 xv = xv4p[k >> 2];
                fma4(acc, xv.x, w0); fma4(acc, xv.y, w1);
                fma4(acc, xv.z, w2); fma4(acc, xv.w, w3);
            }
            ((float4*)(part + kc3 * 256))[job * 32 + lane] = acc;
        }
        __syncthreads();
        if (tid < 256) {
            float d = 0.0f;
#pragma unroll
            for (int i = 0; i < 8; ++i) d += part[i * 256 + tid];
            const int j = rk * 256 + tid;
            out[((size_t)b * S_ + t) * V_ + j] = d + obv[j];
        }
        // no trailing sync needed: next phase 0 writes xin[0..192), disjoint
        // from this phase's xin[192..512) reads; part reuse is fenced by
        // phase 0's __syncthreads.
    }
}

extern "C" void kernel_launch(void* const* d_in, const int* in_sizes, int n_in,
                              void* d_out, int out_size)
{
    const int*   x       = (const int*)d_in[0];
    const float* emb     = (const float*)d_in[1];
    const float* W_ih    = (const float*)d_in[2];
    const float* W_hh    = (const float*)d_in[3];
    const float* b_ih    = (const float*)d_in[4];
    const float* b_hh    = (const float*)d_in[5];
    const float* key_W   = (const float*)d_in[6];
    const float* key_b   = (const float*)d_in[7];
    const float* beta_W  = (const float*)d_in[8];
    const float* beta_b  = (const float*)d_in[9];
    const float* gate_W  = (const float*)d_in[10];
    const float* gate_b  = (const float*)d_in[11];
    const float* shift_W = (const float*)d_in[12];
    const float* shift_b = (const float*)d_in[13];
    const float* gamma_W = (const float*)d_in[14];
    const float* gamma_b = (const float*)d_in[15];
    const float* erase_W = (const float*)d_in[16];
    const float* erase_b = (const float*)d_in[17];
    const float* add_W   = (const float*)d_in[18];
    const float* add_b   = (const float*)d_in[19];
    const float* out_W   = (const float*)d_in[20];
    const float* out_b   = (const float*)d_in[21];
    const float* mem_init= (const float*)d_in[22];
    float* out = (float*)d_out;

    prep_kernel<<<256, 512>>>(W_ih, W_hh, key_W, erase_W, add_W,
                              beta_W, gate_W, gamma_W, shift_W, out_W);

    cudaFuncSetAttribute(ntm_kernel, cudaFuncAttributeMaxDynamicSharedMemorySize,
                         (int)SMEM_BYTES);
    ntm_kernel<<<2 * B_, T_, SMEM_BYTES>>>(
        x, emb, b_ih, b_hh,
        key_b, beta_b, gate_b, shift_b, gamma_b, erase_b, add_b, out_b,
        mem_init, out);
}

// round 14
// speedup vs baseline: 11.5474x; 1.0475x over previous
#include <cuda_runtime.h>
#include <math.h>
#include <float.h>

namespace {
constexpr int B_ = 64;    // batch
constexpr int S_ = 128;   // seq len
constexpr int D_ = 128;   // embed dim
constexpr int V_ = 512;   // vocab
constexpr int N_ = 256;   // memory slots
constexpr int M_ = 64;    // memory width
constexpr int PITCH = 65; // smem pitch for mem (bank-conflict-free)
constexpr int T_ = 512;   // threads per CTA (16 warps)

constexpr int SMEM_FLOATS =
    N_ * PITCH   // mem 16640
    + 512        // xin = [emb128 | rv64 | h256 | rv64] (own batch)
    + 1024       // xo[2][512]: other batch x, double-buffered by step parity
    + 1024       // garr (gate preacts, own batch)
    + 4096       // part (local k/j partials)
    + 4096       // pcl  (cross-CTA LSTM partials, by source rank)
    + 1024       // bias (LSTM gate biases)
    + 512        // obv (out biases)
    + 256        // hb (head biases)
    + 256 + 256  // wprev, wga
    + 64 * 3     // keys, er, ad
    + 512        // rvp
    + 16 + 8;    // red, sc
constexpr size_t SMEM_BYTES = SMEM_FLOATS * sizeof(float);
}

// fp32 transposed weights (static device scratch; no allocation)
__device__ float g_lstmT[448 * 1024];  // [k][gate-row]; k = [emb|rv|h]
__device__ float g_headsT[256 * 256];  // [k][ho], ho >= 198 zero-padded
__device__ float g_outT[320 * 512];    // [k][vocab-row]

__global__ void prep_kernel(
    const float* __restrict__ W_ih, const float* __restrict__ W_hh,
    const float* __restrict__ key_W, const float* __restrict__ erase_W,
    const float* __restrict__ add_W, const float* __restrict__ beta_W,
    const float* __restrict__ gate_W, const float* __restrict__ gamma_W,
    const float* __restrict__ shift_W, const float* __restrict__ out_W)
{
    const int stride = blockDim.x * gridDim.x;
    const int t0 = blockIdx.x * blockDim.x + threadIdx.x;
    for (int i = t0; i < 448 * 1024; i += stride) {
        const int k = i >> 10, row = i & 1023;
        g_lstmT[i] = (k < 192) ? W_ih[row * 192 + k] : W_hh[row * 256 + (k - 192)];
    }
    for (int i = t0; i < 256 * 256; i += stride) {
        const int k = i >> 8, ho = i & 255;
        float v = 0.0f;
        if (ho < 64)        v = key_W[ho * 256 + k];
        else if (ho < 128)  v = erase_W[(ho - 64) * 256 + k];
        else if (ho < 192)  v = add_W[(ho - 128) * 256 + k];
        else if (ho == 192) v = beta_W[k];
        else if (ho == 193) v = gate_W[k];
        else if (ho == 194) v = gamma_W[k];
        else if (ho < 198)  v = shift_W[(ho - 195) * 256 + k];
        g_headsT[i] = v;
    }
    for (int i = t0; i < 320 * 512; i += stride) {
        const int k = i >> 9, row = i & 511;
        g_outT[i] = out_W[row * 320 + k];
    }
}

__device__ __forceinline__ float sigm(float x) { return 1.0f / (1.0f + expf(-x)); }
__device__ __forceinline__ float softplus_(float x) { return log1pf(expf(x)); }

__device__ __forceinline__ void fma4(float4& a, float s, const float4 w) {
    a.x = fmaf(s, w.x, a.x); a.y = fmaf(s, w.y, a.y);
    a.z = fmaf(s, w.z, a.z); a.w = fmaf(s, w.w, a.w);
}

__device__ __forceinline__ float rsum(float v) {
#pragma unroll
    for (int o = 16; o; o >>= 1) v += __shfl_xor_sync(0xffffffffu, v, o);
    return v;
}

__device__ __forceinline__ void cluster_sync_() {
    asm volatile("barrier.cluster.arrive.aligned;" ::: "memory");
    asm volatile("barrier.cluster.wait.aligned;" ::: "memory");
}
// store v into CTA `dst` smem at the same offset as local pointer p
__device__ __forceinline__ void st_peer(float* p, unsigned dst, float v) {
    unsigned a = (unsigned)__cvta_generic_to_shared(p);
    unsigned ra;
    asm volatile("mapa.shared::cluster.u32 %0, %1, %2;" : "=r"(ra) : "r"(a), "r"(dst));
    asm volatile("st.shared::cluster.f32 [%0], %1;" :: "r"(ra), "f"(v) : "memory");
}

// Block sum over 512 threads (16 warps). Entry sync protects `red`.
__device__ __forceinline__ float blk_sum(float v, float* red) {
    v = rsum(v);
    __syncthreads();
    if ((threadIdx.x & 31) == 0) red[threadIdx.x >> 5] = v;
    __syncthreads();
    float s = red[0];
#pragma unroll
    for (int i = 1; i < 16; ++i) s += red[i];
    return s;
}

__global__ void __launch_bounds__(T_, 1) __cluster_dims__(4, 1, 1) ntm_kernel(
    const int* __restrict__ x, const float* __restrict__ emb,
    const float* __restrict__ b_ih, const float* __restrict__ b_hh,
    const float* __restrict__ key_b, const float* __restrict__ beta_b,
    const float* __restrict__ gate_b, const float* __restrict__ shift_b,
    const float* __restrict__ gamma_b, const float* __restrict__ erase_b,
    const float* __restrict__ add_b, const float* __restrict__ out_b,
    const float* __restrict__ mem_init, float* __restrict__ out)
{
    extern __shared__ float sm[];
    const int tid = threadIdx.x;
    const int lane = tid & 31;
    const int wi = tid >> 5;            // warp 0..15
    const int bpair = blockIdx.x >> 2;  // cluster index: 2 batch elements
    unsigned rank;
    asm("mov.u32 %0, %%cluster_ctarank;" : "=r"(rank));
    const int rk = (int)rank;           // 0..3
    const int cb = rk >> 1;             // my batch within pair (0/1)
    const unsigned partner = rank ^ 2u; // same j-half, other batch pair
    const int gb_m = bpair * 2 + cb;        // my global batch
    const int gb_o = bpair * 2 + (1 - cb);  // other global batch

    float* mem   = sm;                 // [N_][PITCH]
    float* xin   = mem + N_ * PITCH;   // 512
    float* xo    = xin + 512;          // [2][512]
    float* garr  = xo + 1024;          // 1024
    float* part  = garr + 1024;        // 4096
    float* pcl   = part + 4096;        // 4096 [src rank][1024]
    float* bias  = pcl + 4096;         // 1024
    float* obv   = bias + 1024;        // 512
    float* hb    = obv + 512;          // 256
    float* wprev = hb + 256;           // 256
    float* wga   = wprev + N_;         // 256
    float* keys  = wga + N_;           // 64
    float* er    = keys + M_;          // 64
    float* ad    = er + M_;            // 64
    float* rvp   = ad + M_;            // 512
    float* red   = rvp + 512;          // 16
    float* sc    = red + 16;           // 8: beta,gate,gamma,knorm,sh0..2

    // ---- init state & cached biases ----
    for (int i = tid; i < N_ * M_; i += T_)
        mem[(i >> 6) * PITCH + (i & 63)] = mem_init[(size_t)gb_m * N_ * M_ + i];
    bias[tid]       = b_ih[tid]       + b_hh[tid];
    bias[512 + tid] = b_ih[512 + tid] + b_hh[512 + tid];
    obv[tid] = out_b[tid];
    xo[tid] = 0.0f; xo[512 + tid] = 0.0f;
    if (tid < 256) {
        float v = 0.0f;
        if (tid < 64)        v = key_b[tid];
        else if (tid < 128)  v = erase_b[tid - 64];
        else if (tid < 192)  v = add_b[tid - 128];
        else if (tid == 192) v = beta_b[0];
        else if (tid == 193) v = gate_b[0];
        else if (tid == 194) v = gamma_b[0];
        else if (tid < 198)  v = shift_b[tid - 195];
        hb[tid] = v;
    }
    if (tid < 256) { xin[192 + tid] = 0.0f; wprev[tid] = 0.0f; }
    if (tid < 64)  { xin[448 + tid] = 0.0f; xin[128 + tid] = 0.0f; }
    float c_reg = 0.0f;                 // valid for tid < 256
    __syncthreads();
    cluster_sync_();   // xo zero-init complete before any peer traffic

    for (int t = 0; t < S_; ++t) {
        float* xot = xo + ((t & 1) << 9);        // other-batch x, this step
        float* xon = xo + (((t + 1) & 1) << 9);  // other-batch x, next step

        // ---- phase 0: emb loads + own rv copy (local only) ----
        const int tok_m = x[gb_m * S_ + t];
        const int tok_o = x[gb_o * S_ + t];
        if (tid < 128)      { xin[tid] = emb[(size_t)tok_m * D_ + tid];
                              xot[tid] = emb[(size_t)tok_o * D_ + tid]; }
        else if (tid < 192)  xin[tid] = xin[tid + 320];
        __syncthreads();

        // ---- phase 1: LSTM preacts, k-quarter per CTA, both batches ----
        {
            const int jb = wi & 7, ks = wi >> 3;
            const int k0 = rk * 112 + ks * 56;
            const int j = jb * 128 + (lane << 2);
            const float* wt = g_lstmT + (size_t)k0 * 1024 + j;
            const float* xm = xin + k0;
            const float* xq = xot + k0;
            float4 am = make_float4(0, 0, 0, 0), ao = am;
#pragma unroll 4
            for (int k = 0; k < 56; ++k) {
                const float4 w = *(const float4*)(wt + (size_t)k * 1024);
                fma4(am, xm[k], w);
                fma4(ao, xq[k], w);
            }
            ((float4*)(part + ks * 2048 + jb * 128))[lane] = am;
            ((float4*)(part + ks * 2048 + 1024 + jb * 128))[lane] = ao;
        }
        __syncthreads();
#pragma unroll
        for (int i = 0; i < 4; ++i) {
            const int idx = i * 512 + tid;          // 0..2047
            const int bt = idx >> 10, j2 = idx & 1023;
            const float v = part[bt * 1024 + j2] + part[2048 + bt * 1024 + j2];
            // dest pair: bt==0 -> my batch owners; bt==1 -> other pair
            const int db = (bt == 0) ? (rk & 2) : ((rk ^ 2) & 2);
            float* dst = &pcl[rk * 1024 + j2];
            if (db == rk)     *dst = v; else st_peer(dst, (unsigned)db, v);
            if (db + 1 == rk) *dst = v; else st_peer(dst, (unsigned)(db + 1), v);
        }
        cluster_sync_();   // sync A: pcl complete everywhere

        garr[tid]       = (pcl[tid] + pcl[1024 + tid])
                        + (pcl[2048 + tid] + pcl[3072 + tid]);
        garr[512 + tid] = (pcl[512 + tid] + pcl[1536 + tid])
                        + (pcl[2560 + tid] + pcl[3584 + tid]);
        __syncthreads();

        // ---- cell update (tid < 256; torch gate order i,f,g,o) + h push ----
        if (tid < 256) {
            const float ig = sigm(garr[tid]        + bias[tid]);
            const float fg = sigm(garr[256 + tid]  + bias[256 + tid]);
            const float gg = tanhf(garr[512 + tid] + bias[512 + tid]);
            const float og = sigm(garr[768 + tid]  + bias[768 + tid]);
            c_reg = fg * c_reg + ig * gg;
            const float hv = og * tanhf(c_reg);
            xin[192 + tid] = hv;
            st_peer(&xot[192 + tid], partner, hv);  // h_t for peer phases 2/8
            st_peer(&xon[192 + tid], partner, hv);  // h_t for peer phase 1 (t+1)
        }
        cluster_sync_();   // sync B1: h_t visible everywhere

        // ---- phase 2: heads, ho-slice per CTA, both batches ----
        {
            const int kg0 = wi * 16;
            float2 am = make_float2(0, 0), ao = am;
            const float* xm = xin + 192 + kg0;
            const float* xq = xot + 192 + kg0;
#pragma unroll
            for (int k = 0; k < 16; ++k) {
                const float2 w = *(const float2*)(g_headsT
                    + (size_t)(kg0 + k) * 256 + rk * 64 + lane * 2);
                am.x = fmaf(xm[k], w.x, am.x); am.y = fmaf(xm[k], w.y, am.y);
                ao.x = fmaf(xq[k], w.x, ao.x); ao.y = fmaf(xq[k], w.y, ao.y);
            }
            ((float2*)(part + wi * 128))[lane] = am;
            ((float2*)(part + wi * 128 + 64))[lane] = ao;
        }
        __syncthreads();
        if (tid < 128) {
            const int bt = tid >> 6, hol = tid & 63;
            float d = 0.0f;
#pragma unroll
            for (int kc = 0; kc < 16; ++kc) d += part[kc * 128 + bt * 64 + hol];
            const int ho = rk * 64 + hol;
            d += hb[ho];
            float* dst = nullptr; float val = 0.0f;
            if (ho < 64)        { dst = &keys[ho];         val = d; }
            else if (ho < 128)  { dst = &er[ho - 64];      val = sigm(d); }
            else if (ho < 192)  { dst = &ad[ho - 128];     val = tanhf(d); }
            else if (ho == 192) { dst = &sc[0];            val = softplus_(d); }
            else if (ho == 193) { dst = &sc[1];            val = sigm(d); }
            else if (ho == 194) { dst = &sc[2];            val = 1.0f + softplus_(d); }
            else if (ho < 198)  { dst = &sc[4 + ho - 195]; val = d; }
            if (dst) {
                const int db = (bt == 0) ? (rk & 2) : ((rk ^ 2) & 2);
                if (db == rk)     *dst = val; else st_peer(dst, (unsigned)db, val);
                if (db + 1 == rk) *dst = val; else st_peer(dst, (unsigned)(db + 1), val);
            }
        }
        cluster_sync_();   // sync B: keys/er/ad/sc complete everywhere

        // ---- phase 3: shift softmax (t0) + key norm (warp 1) ----
        if (tid == 0) {
            const float s0 = sc[4], s1 = sc[5], s2 = sc[6];
            const float mx = fmaxf(s0, fmaxf(s1, s2));
            const float e0 = expf(s0 - mx), e1 = expf(s1 - mx), e2 = expf(s2 - mx);
            const float inv = 1.0f / (e0 + e1 + e2);
            sc[4] = e0 * inv; sc[5] = e1 * inv; sc[6] = e2 * inv;
        } else if (tid >= 32 && tid < 64) {
            const int l = tid - 32;
            float v = keys[l] * keys[l] + keys[l + 32] * keys[l + 32];
#pragma unroll
            for (int o = 16; o; o >>= 1) v += __shfl_xor_sync(0xffffffffu, v, o);
            if (l == 0) sc[3] = fmaxf(sqrtf(v), 1e-12f);
        }
        __syncthreads();

        const float beta = sc[0], gatev = sc[1], gammav = sc[2], knorm = sc[3];
        const float sh0 = sc[4], sh1 = sc[5], sh2 = sc[6];

        // ---- phase 4: content addressing (2 threads per slot; replicated) ----
        {
            const int slot = tid >> 1, q = tid & 1;
            const float* mrow = mem + slot * PITCH + q * 32;
            const float* kq = keys + q * 32;
            float dot = 0.0f, sq = 0.0f;
#pragma unroll 8
            for (int j = 0; j < 32; ++j) {
                const float v = mrow[j];
                dot += v * kq[j];
                sq += v * v;
            }
            dot += __shfl_xor_sync(0xffffffffu, dot, 1);
            sq  += __shfl_xor_sync(0xffffffffu, sq, 1);
            const float sim = dot / (fmaxf(sqrtf(sq), 1e-12f) * knorm);
            const float e = expf(beta * sim);
            const float ssum = blk_sum(q == 0 ? e : 0.0f, red);
            if (q == 0) {
                const float wc = e / ssum;
                wga[slot] = gatev * wc + (1.0f - gatev) * wprev[slot];
            }
        }
        __syncthreads();

        // ---- phase 5: circular conv + sharpening (tid < 256; replicated) ----
        {
            float ws = 0.0f;
            if (tid < 256) {
                const float wt_ = sh0 * wga[(tid + 1) & 255] + sh1 * wga[tid]
                                + sh2 * wga[(tid + 255) & 255];
                ws = powf(wt_, gammav);
            }
            const float wsum = blk_sum(ws, red);
            if (tid < 256) {
                const float w = ws / wsum;
                wprev[tid] = w;
                wga[tid] = w;
            }
        }
        __syncthreads();

        // ---- phase 6: rv = w @ mem (replicated) ----
        {
            const int m = tid & 63, g = tid >> 6;
            const float* base = mem + (g * 32) * PITCH + m;
            const float* wp = wga + g * 32;
            float s = 0.0f;
#pragma unroll 8
            for (int n = 0; n < 32; ++n) s += wp[n] * base[n * PITCH];
            rvp[g * 64 + m] = s;
        }
        __syncthreads();

        if (tid < 64) {
            float r_ = 0.0f;
#pragma unroll
            for (int g = 0; g < 8; ++g) r_ += rvp[g * 64 + tid];
            xin[448 + tid] = r_;
            st_peer(&xot[448 + tid], partner, r_);  // rv_t for peer phase 8
            st_peer(&xon[128 + tid], partner, r_);  // rv_t for peer LSTM (t+1)
        }

        // ---- phase 7: memory erase/add (2 threads per slot; replicated) ----
        {
            const int slot = tid >> 1, q = tid & 1;
            const float wn = wga[slot];
            float* mrow = mem + slot * PITCH + q * 32;
            const float* eq = er + q * 32;
            const float* aq = ad + q * 32;
#pragma unroll 8
            for (int j = 0; j < 32; ++j)
                mrow[j] = mrow[j] * (1.0f - wn * eq[j]) + wn * aq[j];
        }
        cluster_sync_();   // sync C: rv_t visible everywhere (also local fence)

        // ---- phase 8: output logits, j-slice per CTA, both batches ----
        {
            const int kg0 = wi * 20;
            const int j4 = rk * 128 + (lane << 2);
            const float* wt = g_outT + (size_t)kg0 * 512 + j4;
            const float* xm = xin + 192 + kg0;
            const float* xq = xot + 192 + kg0;
            float4 am = make_float4(0, 0, 0, 0), ao = am;
#pragma unroll 4
            for (int k = 0; k < 20; ++k) {
                const float4 w = *(const float4*)(wt + (size_t)k * 512);
                fma4(am, xm[k], w);
                fma4(ao, xq[k], w);
            }
            ((float4*)(part + wi * 256))[lane] = am;
            ((float4*)(part + wi * 256 + 128))[lane] = ao;
        }
        __syncthreads();
        if (tid < 256) {
            const int bt = tid >> 7, jl = tid & 127;
            float d = 0.0f;
#pragma unroll
            for (int kc = 0; kc < 16; ++kc) d += part[kc * 256 + bt * 128 + jl];
            const int gb = (bt == 0) ? gb_m : gb_o;
            const int j = rk * 128 + jl;
            out[((size_t)gb * S_ + t) * V_ + j] = d + obv[j];
        }
        __syncthreads();
    }
    cluster_sync_();   // no CTA exits while peers may still read/write
}

extern "C" void kernel_launch(void* const* d_in, const int* in_sizes, int n_in,
                              void* d_out, int out_size)
{
    const int*   x       = (const int*)d_in[0];
    const float* emb     = (const float*)d_in[1];
    const float* W_ih    = (const float*)d_in[2];
    const float* W_hh    = (const float*)d_in[3];
    const float* b_ih    = (const float*)d_in[4];
    const float* b_hh    = (const float*)d_in[5];
    const float* key_W   = (const float*)d_in[6];
    const float* key_b   = (const float*)d_in[7];
    const float* beta_W  = (const float*)d_in[8];
    const float* beta_b  = (const float*)d_in[9];
    const float* gate_W  = (const float*)d_in[10];
    const float* gate_b  = (const float*)d_in[11];
    const float* shift_W = (const float*)d_in[12];
    const float* shift_b = (const float*)d_in[13];
    const float* gamma_W = (const float*)d_in[14];
    const float* gamma_b = (const float*)d_in[15];
    const float* erase_W = (const float*)d_in[16];
    const float* erase_b = (const float*)d_in[17];
    const float* add_W   = (const float*)d_in[18];
    const float* add_b   = (const float*)d_in[19];
    const float* out_W   = (const float*)d_in[20];
    const float* out_b   = (const float*)d_in[21];
    const float* mem_init= (const float*)d_in[22];
    float* out = (float*)d_out;

    prep_kernel<<<256, 512>>>(W_ih, W_hh, key_W, erase_W, add_W,
                              beta_W, gate_W, gamma_W, shift_W, out_W);

    cudaFuncSetAttribute(ntm_kernel, cudaFuncAttributeMaxDynamicSharedMemorySize,
                         (int)SMEM_BYTES);
    ntm_kernel<<<2 * B_, T_, SMEM_BYTES>>>(
        x, emb, b_ih, b_hh,
        key_b, beta_b, gate_b, shift_b, gamma_b, erase_b, add_b, out_b,
        mem_init, out);
}